// round 14
// baseline (speedup 1.0000x reference)
#include <cuda_runtime.h>
#include <cuda_fp16.h>
#include <cstdint>
#include <cstddef>

// ---------------- scratch (__device__ globals; no allocations) ----------------
__device__ float g_p1[4*64*32*48];
__device__ float g_p2[4*128*16*24];
__device__ float g_p3[4*256*8*12];
__device__ __half g_a4[4*128*2304];          // im2col of p3 (rows 96..127 zero)
__device__ __half g_w4hi[512*2304];
__device__ __half g_w4lo[512*2304];
__device__ float g_cpart[4*4*512*96];        // conv4 k-split partials
__device__ float g_u[4*96*256];
__device__ float g_v[4*96*256];
__device__ float g_ws[4*256];
__device__ __half g_a16[36864*256];
__device__ __half g_wthi[3072*256];
__device__ __half g_w2thi[256*256];
__device__ float g_part[288*3072];

// ---------------- helpers ----------------
__device__ __forceinline__ uint32_t smem_u32(const void* p) {
    uint32_t a;
    asm("{ .reg .u64 t; cvta.to.shared.u64 t, %1; cvt.u32.u64 %0, t; }" : "=r"(a) : "l"(p));
    return a;
}
__device__ __forceinline__ void ldm_x4(uint32_t& r0, uint32_t& r1, uint32_t& r2, uint32_t& r3, uint32_t addr) {
    asm volatile("ldmatrix.sync.aligned.m8n8.x4.shared.b16 {%0,%1,%2,%3}, [%4];"
                 : "=r"(r0), "=r"(r1), "=r"(r2), "=r"(r3) : "r"(addr));
}
__device__ __forceinline__ void mma_f16(float* c, const uint32_t* a, uint32_t b0, uint32_t b1) {
    asm volatile("mma.sync.aligned.m16n8k16.row.col.f32.f16.f16.f32 "
                 "{%0,%1,%2,%3}, {%4,%5,%6,%7}, {%8,%9}, {%0,%1,%2,%3};"
                 : "+f"(c[0]), "+f"(c[1]), "+f"(c[2]), "+f"(c[3])
                 : "r"(a[0]), "r"(a[1]), "r"(a[2]), "r"(a[3]), "r"(b0), "r"(b1));
}
__device__ __forceinline__ void cp16(uint32_t dst, const void* src) {
    asm volatile("cp.async.ca.shared.global [%0], [%1], 16;" :: "r"(dst), "l"(src));
}
#define CP_COMMIT() asm volatile("cp.async.commit_group;" ::: "memory")
#define CP_WAIT0()  asm volatile("cp.async.wait_group 0;" ::: "memory")

// ---------------- 3x3 SAME conv + bias + relu + fused 2x2 maxpool ----------------
template<int IC,int ICC,int OC,int OCB,int OCPT,int H,int W,int TH>
__global__ void conv3x3_pool(const float* __restrict__ in,
                             const float* __restrict__ wgt,
                             const float* __restrict__ bias,
                             float* __restrict__ out)
{
    constexpr int PTH = (TH/2)*(W/2);
    constexpr int BY  = OCB/OCPT;
    constexpr int NT  = PTH*BY;
    constexpr int WP  = W+2;
    constexpr int THP = TH+2;
    __shared__ float s_in[ICC*THP*WP];
    __shared__ float s_w[ICC*OCB*9];

    const int b   = blockIdx.x;
    const int oc0 = blockIdx.y*OCB;
    const int y0  = blockIdx.z*TH;
    const int tx  = threadIdx.x;
    const int ty  = threadIdx.y;
    const int tid = ty*PTH + tx;

    float acc[4][OCPT];
    #pragma unroll
    for (int p=0;p<4;p++)
        #pragma unroll
        for (int o=0;o<OCPT;o++) acc[p][o]=0.f;

    const int ppy = tx/(W/2), ppx = tx%(W/2);
    int ly[4], lx[4];
    #pragma unroll
    for (int p=0;p<4;p++){ ly[p]=2*ppy+(p>>1); lx[p]=2*ppx+(p&1); }

    for (int c0=0;c0<IC;c0+=ICC) {
        __syncthreads();
        for (int idx=tid; idx<ICC*THP*WP; idx+=NT) {
            int ic = idx/(THP*WP); int r = idx - ic*(THP*WP);
            int yy = r/WP, xx = r - yy*WP;
            int gy = y0+yy-1, gx = xx-1;
            float vv=0.f;
            if (gy>=0 && gy<H && gx>=0 && gx<W)
                vv = in[((b*IC + c0+ic)*H + gy)*W + gx];
            s_in[idx]=vv;
        }
        for (int idx=tid; idx<ICC*OCB*9; idx+=NT) {
            int ic = idx/(OCB*9); int r = idx - ic*(OCB*9);
            int oc = r/9, k = r - oc*9;
            s_w[idx] = wgt[((oc0+oc)*IC + c0+ic)*9 + k];
        }
        __syncthreads();
        for (int ic=0; ic<ICC; ic++) {
            #pragma unroll
            for (int k=0;k<9;k++) {
                float wk[OCPT];
                #pragma unroll
                for (int o=0;o<OCPT;o++)
                    wk[o] = s_w[ic*OCB*9 + (ty*OCPT+o)*9 + k];
                #pragma unroll
                for (int p=0;p<4;p++) {
                    float iv = s_in[ic*THP*WP + (ly[p]+k/3)*WP + lx[p]+(k%3)];
                    #pragma unroll
                    for (int o=0;o<OCPT;o++) acc[p][o]=fmaf(iv,wk[o],acc[p][o]);
                }
            }
        }
    }
    #pragma unroll
    for (int o=0;o<OCPT;o++){
        int oc = oc0 + ty*OCPT + o;
        float m = fmaxf(fmaxf(acc[0][o],acc[1][o]), fmaxf(acc[2][o],acc[3][o]));
        out[((b*OC + oc)*(H/2) + (y0>>1)+ppy)*(W/2) + ppx] = fmaxf(m + bias[oc], 0.f);
    }
}

// ---------------- fused prep: w3 fp16 | w2 fp16 | w4 hi/lo | im2col of p3 ----------
__global__ void prep_all_k(const float* __restrict__ w3, const float* __restrict__ w2,
                           const float* __restrict__ w4, const float* __restrict__ p3,
                           __half* __restrict__ w3hi, __half* __restrict__ w2hi,
                           __half* __restrict__ w4hi, __half* __restrict__ w4lo,
                           __half* __restrict__ A)
{
    int idx = blockIdx.x*256 + threadIdx.x;
    if (idx < 256*3072) {
        int k = idx/3072, n = idx - k*3072;
        w3hi[n*256+k] = __float2half(w3[idx]);
    } else if (idx < 256*3072 + 256*256) {
        int i2 = idx - 256*3072;
        int k = i2 >> 8, n = i2 & 255;
        w2hi[n*256+k] = __float2half(w2[i2]);
    } else if (idx < 256*3072 + 256*256 + 512*2304) {
        int i3 = idx - 256*3072 - 256*256;
        float vv = w4[i3];                  // e4w already [oc][ic*9]
        __half h = __float2half(vv);
        w4hi[i3] = h;
        w4lo[i3] = __float2half(vv - __half2float(h));
    } else {
        int i4 = idx - 256*3072 - 256*256 - 512*2304;
        if (i4 >= 4*128*2304) return;
        int c = i4 % 2304; int r = i4 / 2304;
        int b = r >> 7, px = r & 127;
        float v = 0.f;
        if (px < 96) {
            int ic = c/9, k = c - ic*9;
            int y = px/12, x = px - 12*y;
            int gy = y + k/3 - 1, gx = x + (k%3) - 1;
            if (gy>=0 && gy<8 && gx>=0 && gx<12)
                v = p3[((b*256+ic)*8 + gy)*12 + gx];
        }
        A[i4] = __float2half(v);
    }
}

// ---------------- conv4 GEMM: part[ks] = A[b] @ (W4hi+W4lo)^T, K-split x4 ----------
static constexpr int C4_TILE  = 18432;
static constexpr int C4_STAGE = 3*C4_TILE;
static constexpr int C4_DYN   = 2*C4_STAGE;
__global__ void __launch_bounds__(256,1) conv4_mma_k(
    const __half* __restrict__ A,
    const __half* __restrict__ whi, const __half* __restrict__ wlo,
    float* __restrict__ part)
{
    extern __shared__ __align__(16) char dsm[];
    const int tid  = threadIdx.x;
    const int wid  = tid >> 5;
    const int lane = tid & 31;
    const int wm   = wid >> 1;
    const int wn   = wid & 1;
    const int b    = blockIdx.x;
    const int nt0  = blockIdx.y;
    const int ks   = blockIdx.z;

    const __half* Aa = A   + (size_t)(b*128)*2304   + ks*576;
    const __half* Bh = whi + (size_t)(nt0*128)*2304 + ks*576;
    const __half* Bl = wlo + (size_t)(nt0*128)*2304 + ks*576;
    const uint32_t dsb = smem_u32(dsm);

    float c[2][8][4];
    #pragma unroll
    for (int mt=0;mt<2;mt++)
        #pragma unroll
        for (int nt=0;nt<8;nt++)
            #pragma unroll
            for (int e=0;e<4;e++) c[mt][nt][e]=0.f;

    auto issue = [&](int cn, int stage) {
        const int koff = cn*64;
        const uint32_t dA = dsb + stage*C4_STAGE;
        const uint32_t dH = dA + C4_TILE;
        const uint32_t dL = dH + C4_TILE;
        #pragma unroll
        for (int i2=0;i2<4;i2++){
            int cidx = tid + i2*256;
            int row = cidx >> 3, g = cidx & 7;
            cp16(dA + row*144 + g*16, Aa + (size_t)row*2304 + koff + g*8);
            cp16(dH + row*144 + g*16, Bh + (size_t)row*2304 + koff + g*8);
            cp16(dL + row*144 + g*16, Bl + (size_t)row*2304 + koff + g*8);
        }
        CP_COMMIT();
    };

    issue(0, 0);

    for (int ch = 0; ch < 9; ch++) {
        CP_WAIT0();
        __syncthreads();
        if (ch < 8) issue(ch+1, (ch+1)&1);

        const uint32_t sAb = dsb + (ch&1)*C4_STAGE;
        const uint32_t sH  = sAb + C4_TILE;
        const uint32_t sL  = sH + C4_TILE;
        #pragma unroll
        for (int kstep=0; kstep<4; kstep++) {
            uint32_t a[2][4];
            #pragma unroll
            for (int mt=0; mt<2; mt++) {
                int row = wm*32 + mt*16 + (lane&7) + ((lane>>3)&1)*8;
                int col = ((lane>>4)&1)*8 + kstep*16;
                ldm_x4(a[mt][0],a[mt][1],a[mt][2],a[mt][3], sAb + (row*72 + col)*2);
            }
            #pragma unroll
            for (int ntp=0; ntp<4; ntp++) {
                int rn = wn*64 + ntp*16 + (lane&7) + ((lane>>4)&1)*8;
                int ck = ((lane>>3)&1)*8 + kstep*16;
                uint32_t r0,r1,r2,r3;
                ldm_x4(r0,r1,r2,r3, sH + (rn*72 + ck)*2);
                mma_f16(c[0][2*ntp],   a[0], r0, r1);
                mma_f16(c[0][2*ntp+1], a[0], r2, r3);
                mma_f16(c[1][2*ntp],   a[1], r0, r1);
                mma_f16(c[1][2*ntp+1], a[1], r2, r3);
                ldm_x4(r0,r1,r2,r3, sL + (rn*72 + ck)*2);
                mma_f16(c[0][2*ntp],   a[0], r0, r1);
                mma_f16(c[0][2*ntp+1], a[0], r2, r3);
                mma_f16(c[1][2*ntp],   a[1], r0, r1);
                mma_f16(c[1][2*ntp+1], a[1], r2, r3);
            }
        }
        __syncthreads();
    }

    #pragma unroll
    for (int mt=0; mt<2; mt++) {
        int row = wm*32 + mt*16 + (lane>>2);
        #pragma unroll
        for (int nt=0; nt<8; nt++) {
            int col = nt0*128 + wn*64 + nt*8 + (lane&3)*2;
            size_t base = ((size_t)(ks*4 + b)*512 + col)*96;
            if (row < 96) {
                part[base + row]      = c[mt][nt][0];
                part[base + 96 + row] = c[mt][nt][1];
            }
            if (row + 8 < 96) {
                part[base + row + 8]      = c[mt][nt][2];
                part[base + 96 + row + 8] = c[mt][nt][3];
            }
        }
    }
}

// ---------------- u,v = F @ A, F @ B ; blockIdx.y==8 -> ws ----------------
__global__ void __launch_bounds__(256) uvws_k(const float* __restrict__ cpart,
                                              const float* __restrict__ e4b,
                                              const float* __restrict__ g1w,
                                              const float* __restrict__ g1b,
                                              const float* __restrict__ sen,
                                              float* __restrict__ u, float* __restrict__ v,
                                              float* __restrict__ ws)
{
    __shared__ float sF[128*96];
    const int b  = blockIdx.x;
    const int tid = threadIdx.x;
    const int PS = 4*512*96;

    if (blockIdx.y == 8) {
        float* ss = sF;
        const int n = tid;
        for (int k=n;k<384;k+=256) ss[k]=sen[b*384+k];
        __syncthreads();
        float acc = g1b[n];
        for (int k=0;k<384;k++) acc = fmaf(ss[k], g1w[(1028+k)*256+n], acc);
        ws[b*256+n]=acc;
        return;
    }

    const int n0 = blockIdx.y*32;
    const int n  = tid & 31;
    const int pg = tid >> 5;
    float au[12], av[12];
    #pragma unroll
    for (int i=0;i<12;i++){ au[i]=0.f; av[i]=0.f; }

    for (int k0=0; k0<512; k0+=128) {
        __syncthreads();
        for (int idx=tid; idx<128*96; idx+=256) {
            int kk = idx/96, p = idx - kk*96;
            int base = (b*512 + k0 + kk)*96 + p;
            float vv = cpart[base] + cpart[base+PS] + cpart[base+2*PS] + cpart[base+3*PS]
                     + e4b[k0+kk];
            sF[kk*96 + p] = fmaxf(vv, 0.f);
        }
        __syncthreads();
        for (int kk=0; kk<128; kk++) {
            float wu = g1w[(k0+kk)*256 + n0 + n];
            float wv = g1w[(514 + k0+kk)*256 + n0 + n];
            const float* fr = &sF[kk*96 + pg*12];
            #pragma unroll
            for (int i=0;i<12;i++){
                float f = fr[i];
                au[i] = fmaf(f, wu, au[i]);
                av[i] = fmaf(f, wv, av[i]);
            }
        }
    }
    {
        float wu0 = g1w[512*256 + n0 + n], wu1 = g1w[513*256 + n0 + n];
        float wv0 = g1w[(514+512)*256 + n0 + n], wv1 = g1w[(514+513)*256 + n0 + n];
        #pragma unroll
        for (int i=0;i<12;i++){
            int p = pg*12 + i;
            float fx = -1.f + (2.f*(float)(p/8))/11.f;
            float fy = -1.f + (2.f*(float)(p%8))/7.f;
            au[i] += fx*wu0 + fy*wu1;
            av[i] += fx*wv0 + fy*wv1;
        }
    }
    #pragma unroll
    for (int i=0;i<12;i++){
        int p = pg*12 + i;
        u[(b*96+p)*256 + n0 + n] = au[i];
        v[(b*96+p)*256 + n0 + n] = av[i];
    }
}

// ---------------- h2 = relu(h1 @ W2 + b2) -> fp16, single-pass mma ----------------
static constexpr int H2_DYN = 30720;   // A 10240 + B 2 stages x 10240
__global__ void __launch_bounds__(256,2) h2_mma_k(
    const float* __restrict__ u, const float* __restrict__ v,
    const float* __restrict__ ws,
    const __half* __restrict__ w2thi,
    const float* __restrict__ b2, __half* __restrict__ a16)
{
    extern __shared__ __align__(16) char dsm[];
    __half* sA = (__half*)dsm;                       // 128*40
    __shared__ float sws[256];
    __shared__ float sb2[128];

    const int tid = threadIdx.x;
    const int wid = tid >> 5, lane = tid & 31;
    const int wm = wid >> 1, wn = wid & 1;
    const int r0 = blockIdx.x*128;
    const int n0 = blockIdx.y*128;
    const int b  = r0/9216;

    sws[tid] = ws[b*256 + tid];
    if (tid < 128) sb2[tid] = b2[n0 + tid];

    const int arow = tid >> 1;
    const int kh   = (tid & 1)*16;
    const int rr   = (r0 + arow) - b*9216;
    const int ii   = rr/96, jj = rr - ii*96;
    const float* up = u + (b*96 + jj)*256 + kh;
    const float* vp = v + (b*96 + ii)*256 + kh;

    const __half* Wh = w2thi + n0*256;
    const uint32_t dsb = smem_u32(dsm);

    auto issueB = [&](int cn, int stage) {
        const int koff = cn*32;
        const uint32_t dH = dsb + 10240 + stage*10240;
        #pragma unroll
        for (int i2=0;i2<2;i2++){
            int cidx = tid + i2*256;
            int row = cidx >> 2, g = cidx & 3;
            cp16(dH + row*80 + g*16, Wh + row*256 + koff + g*8);
        }
        CP_COMMIT();
    };

    float c[2][8][4];
    #pragma unroll
    for (int mt=0;mt<2;mt++)
        #pragma unroll
        for (int nt=0;nt<8;nt++)
            #pragma unroll
            for (int e=0;e<4;e++) c[mt][nt][e]=0.f;

    issueB(0, 0);

    for (int ch = 0; ch < 8; ch++) {
        CP_WAIT0();
        __syncthreads();
        {
            const int koff = ch*32;
            float uf[16], vf[16];
            #pragma unroll
            for (int q=0;q<4;q++){
                *(float4*)&uf[q*4] = *(const float4*)(up + koff + q*4);
                *(float4*)&vf[q*4] = *(const float4*)(vp + koff + q*4);
            }
            __half hv[16];
            const float* wsp = &sws[koff + kh];
            #pragma unroll
            for (int e=0;e<16;e++) hv[e] = __float2half(fmaxf(uf[e]+vf[e]+wsp[e], 0.f));
            *(uint4*)&sA[arow*40 + kh]     = *(const uint4*)hv;
            *(uint4*)&sA[arow*40 + kh + 8] = *(const uint4*)(hv+8);
        }
        if (ch < 7) issueB(ch+1, (ch+1)&1);
        __syncthreads();

        const uint32_t sAb = dsb;
        const uint32_t sH = dsb + 10240 + (ch&1)*10240;
        #pragma unroll
        for (int ks=0; ks<2; ks++) {
            uint32_t a[2][4];
            #pragma unroll
            for (int mt=0; mt<2; mt++) {
                int row = wm*32 + mt*16 + (lane&7) + ((lane>>3)&1)*8;
                int col = ((lane>>4)&1)*8 + ks*16;
                ldm_x4(a[mt][0],a[mt][1],a[mt][2],a[mt][3], sAb + (row*40 + col)*2);
            }
            #pragma unroll
            for (int ntp=0; ntp<4; ntp++) {
                int rn = wn*64 + ntp*16 + (lane&7) + ((lane>>4)&1)*8;
                int ck = ((lane>>3)&1)*8 + ks*16;
                uint32_t r0r,r1r,r2r,r3r;
                ldm_x4(r0r,r1r,r2r,r3r, sH + (rn*40 + ck)*2);
                mma_f16(c[0][2*ntp],   a[0], r0r, r1r);
                mma_f16(c[0][2*ntp+1], a[0], r2r, r3r);
                mma_f16(c[1][2*ntp],   a[1], r0r, r1r);
                mma_f16(c[1][2*ntp+1], a[1], r2r, r3r);
            }
        }
    }

    #pragma unroll
    for (int mt=0; mt<2; mt++) {
        int row_l = r0 + wm*32 + mt*16 + (lane>>2);
        #pragma unroll
        for (int nt=0; nt<8; nt++) {
            int col = n0 + wn*64 + nt*8 + (lane&3)*2;
            float b0 = sb2[col - n0], b1 = sb2[col - n0 + 1];
            __half2 lo2 = __floats2half2_rn(fmaxf(c[mt][nt][0]+b0,0.f), fmaxf(c[mt][nt][1]+b1,0.f));
            __half2 hi2 = __floats2half2_rn(fmaxf(c[mt][nt][2]+b0,0.f), fmaxf(c[mt][nt][3]+b1,0.f));
            *(__half2*)&a16[(size_t)row_l*256 + col]     = lo2;
            *(__half2*)&a16[(size_t)(row_l+8)*256 + col] = hi2;
        }
    }
}

// ---------------- g3: single fp16 pass, BK=64 (4 fat chunks), 2-stage cp.async ----
static constexpr int G3_TILE  = 18432;
static constexpr int G3_STAGE = 2*G3_TILE;
static constexpr int G3_DYN   = 2*G3_STAGE;
__global__ void __launch_bounds__(256,2) g3_mma_k(
    const __half* __restrict__ a16,
    const __half* __restrict__ wthi,
    const float* __restrict__ b3, float* __restrict__ part)
{
    extern __shared__ __align__(16) char dsm[];
    __shared__ float sbias[128];
    __shared__ float spart[4][128];

    const int tid  = threadIdx.x;
    const int wid  = tid >> 5;
    const int lane = tid & 31;
    const int wm   = wid >> 1;
    const int wn   = wid & 1;
    const int mtile = blockIdx.x;
    const int ntile = blockIdx.y;

    if (tid < 128) sbias[tid] = b3[ntile*128 + tid];

    const __half* Aa = a16  + (size_t)mtile*128*256;
    const __half* Wh = wthi + (size_t)ntile*128*256;
    const uint32_t dsb = smem_u32(dsm);

    float c[2][8][4];
    #pragma unroll
    for (int mt=0;mt<2;mt++)
        #pragma unroll
        for (int nt=0;nt<8;nt++)
            #pragma unroll
            for (int e=0;e<4;e++) c[mt][nt][e]=0.f;

    auto issue = [&](int cn, int stage) {
        const int koff = cn*64;
        const uint32_t dA = dsb + stage*G3_STAGE;
        const uint32_t dB = dA + G3_TILE;
        #pragma unroll
        for (int i2=0;i2<4;i2++){
            int cidx = tid + i2*256;
            int row = cidx >> 3, g = cidx & 7;
            cp16(dA + row*144 + g*16, Aa + row*256 + koff + g*8);
            cp16(dB + row*144 + g*16, Wh + row*256 + koff + g*8);
        }
        CP_COMMIT();
    };

    issue(0, 0);

    for (int ch = 0; ch < 4; ch++) {
        CP_WAIT0();
        __syncthreads();
        if (ch < 3) issue(ch+1, (ch+1)&1);

        const uint32_t sAb = dsb + (ch&1)*G3_STAGE;
        const uint32_t sB  = sAb + G3_TILE;
        #pragma unroll
        for (int ks=0; ks<4; ks++) {
            uint32_t a[2][4];
            #pragma unroll
            for (int mt=0; mt<2; mt++) {
                int row = wm*32 + mt*16 + (lane&7) + ((lane>>3)&1)*8;
                int col = ((lane>>4)&1)*8 + ks*16;
                ldm_x4(a[mt][0],a[mt][1],a[mt][2],a[mt][3], sAb + (row*72 + col)*2);
            }
            #pragma unroll
            for (int ntp=0; ntp<4; ntp++) {
                int rn = wn*64 + ntp*16 + (lane&7) + ((lane>>4)&1)*8;
                int ck = ((lane>>3)&1)*8 + ks*16;
                uint32_t r0,r1,r2,r3;
                ldm_x4(r0,r1,r2,r3, sB + (rn*72 + ck)*2);
                mma_f16(c[0][2*ntp],   a[0], r0, r1);
                mma_f16(c[0][2*ntp+1], a[0], r2, r3);
                mma_f16(c[1][2*ntp],   a[1], r0, r1);
                mma_f16(c[1][2*ntp+1], a[1], r2, r3);
            }
        }
        __syncthreads();
    }

    #pragma unroll
    for (int nt=0; nt<8; nt++) {
        int ncol = wn*64 + nt*8 + (lane&3)*2;
        float bias0 = sbias[ncol];
        float bias1 = sbias[ncol+1];
        float t0 = 0.f, t1 = 0.f;
        #pragma unroll
        for (int mt=0; mt<2; mt++) {
            t0 += fmaxf(c[mt][nt][0] + bias0, 0.f) + fmaxf(c[mt][nt][2] + bias0, 0.f);
            t1 += fmaxf(c[mt][nt][1] + bias1, 0.f) + fmaxf(c[mt][nt][3] + bias1, 0.f);
        }
        t0 += __shfl_xor_sync(0xFFFFFFFFu, t0, 4);
        t0 += __shfl_xor_sync(0xFFFFFFFFu, t0, 8);
        t0 += __shfl_xor_sync(0xFFFFFFFFu, t0, 16);
        t1 += __shfl_xor_sync(0xFFFFFFFFu, t1, 4);
        t1 += __shfl_xor_sync(0xFFFFFFFFu, t1, 8);
        t1 += __shfl_xor_sync(0xFFFFFFFFu, t1, 16);
        if (lane < 4) {
            spart[wm][wn*64 + nt*8 + lane*2]     = t0;
            spart[wm][wn*64 + nt*8 + lane*2 + 1] = t1;
        }
    }
    __syncthreads();
    if (tid < 128) {
        float s = spart[0][tid] + spart[1][tid] + spart[2][tid] + spart[3][tid];
        part[(size_t)mtile*3072 + ntile*128 + tid] = s;
    }
}

// ---------------- final reduce over 72 row-tiles per batch ----------------
__global__ void final_reduce_k(const float* __restrict__ part, float* __restrict__ outp)
{
    int idx = blockIdx.x*blockDim.x + threadIdx.x;
    if (idx >= 4*3072) return;
    int b = idx/3072, n = idx - b*3072;
    float s = 0.f;
    for (int t=0;t<72;t++) s += part[(b*72+t)*3072 + n];
    outp[idx] = s;
}

// ---------------- launch ----------------
extern "C" void kernel_launch(void* const* d_in, const int* in_sizes, int n_in,
                              void* d_out, int out_size)
{
    const float* x      = (const float*)d_in[0];
    const float* sen    = (const float*)d_in[1];
    const float* e1w    = (const float*)d_in[2];
    const float* e1b    = (const float*)d_in[3];
    const float* e2w    = (const float*)d_in[4];
    const float* e2b    = (const float*)d_in[5];
    const float* e3w    = (const float*)d_in[6];
    const float* e3b    = (const float*)d_in[7];
    const float* e4w    = (const float*)d_in[8];
    const float* e4b    = (const float*)d_in[9];
    const float* g1w    = (const float*)d_in[10];
    const float* g1b    = (const float*)d_in[11];
    const float* g2w    = (const float*)d_in[12];
    const float* g2b    = (const float*)d_in[13];
    const float* g3w    = (const float*)d_in[14];
    const float* g3b    = (const float*)d_in[15];
    float* outp = (float*)d_out;

    float *pp1,*pp2,*pp3,*pcpart,*pu,*pv,*pws,*ppart;
    __half *pa4,*pw4hi,*pw4lo,*pa16,*pwthi,*pw2thi;
    cudaGetSymbolAddress((void**)&pp1,  g_p1);
    cudaGetSymbolAddress((void**)&pp2,  g_p2);
    cudaGetSymbolAddress((void**)&pp3,  g_p3);
    cudaGetSymbolAddress((void**)&pa4,  g_a4);
    cudaGetSymbolAddress((void**)&pw4hi,g_w4hi);
    cudaGetSymbolAddress((void**)&pw4lo,g_w4lo);
    cudaGetSymbolAddress((void**)&pcpart,g_cpart);
    cudaGetSymbolAddress((void**)&pu,   g_u);
    cudaGetSymbolAddress((void**)&pv,   g_v);
    cudaGetSymbolAddress((void**)&pws,  g_ws);
    cudaGetSymbolAddress((void**)&pa16, g_a16);
    cudaGetSymbolAddress((void**)&pwthi,g_wthi);
    cudaGetSymbolAddress((void**)&pw2thi,g_w2thi);
    cudaGetSymbolAddress((void**)&ppart,g_part);

    cudaFuncSetAttribute(h2_mma_k, cudaFuncAttributeMaxDynamicSharedMemorySize, H2_DYN);
    cudaFuncSetAttribute(g3_mma_k, cudaFuncAttributeMaxDynamicSharedMemorySize, G3_DYN);
    cudaFuncSetAttribute(conv4_mma_k, cudaFuncAttributeMaxDynamicSharedMemorySize, C4_DYN);

    // encoder (pool fused; conv4 as tensor-core GEMM)
    conv3x3_pool<3,3,64,32,8,64,96,4><<<dim3(4,2,16), dim3(96,4)>>>(x, e1w, e1b, pp1);
    conv3x3_pool<64,16,128,16,4,32,48,4><<<dim3(4,8,8), dim3(48,4)>>>(pp1, e2w, e2b, pp2);
    conv3x3_pool<128,16,256,16,4,16,24,4><<<dim3(4,16,4), dim3(24,4)>>>(pp2, e3w, e3b, pp3);
    prep_all_k<<<(256*3072+256*256+512*2304+4*128*2304+255)/256,256>>>(
        g3w, g2w, e4w, pp3, pwthi, pw2thi, pw4hi, pw4lo, pa4);
    conv4_mma_k<<<dim3(4,4,4),256,C4_DYN>>>(pa4, pw4hi, pw4lo, pcpart);

    // relation net
    uvws_k<<<dim3(4,9),256>>>(pcpart, e4b, g1w, g1b, sen, pu, pv, pws);
    h2_mma_k<<<dim3(288,2),256,H2_DYN>>>(pu, pv, pws, pw2thi, g2b, pa16);
    g3_mma_k<<<dim3(288,24),256,G3_DYN>>>(pa16, pwthi, g3b, ppart);
    final_reduce_k<<<48,256>>>(ppart, outp);
}

// round 15
// speedup vs baseline: 1.2611x; 1.2611x over previous
#include <cuda_runtime.h>
#include <cuda_fp16.h>
#include <cstdint>
#include <cstddef>

// ---------------- scratch (__device__ globals; no allocations) ----------------
__device__ float g_p1[4*64*32*48];
__device__ float g_p2[4*128*16*24];
__device__ float g_c3part[2*4*256*384];      // conv3 ic-split unpooled partials
__device__ float g_p3[4*256*8*12];
__device__ __half g_a4[4*128*2304];          // im2col of p3 (rows 96..127 zero)
__device__ __half g_w4hi[512*2304];
__device__ __half g_w4lo[512*2304];
__device__ float g_cpart[4*4*512*96];        // conv4 k-split partials
__device__ float g_u[4*96*256];
__device__ float g_v[4*96*256];
__device__ float g_ws[4*256];
__device__ __half g_a16[36864*256];
__device__ __half g_wthi[3072*256];
__device__ __half g_w2thi[256*256];
__device__ float g_part[288*3072];

// ---------------- helpers ----------------
__device__ __forceinline__ uint32_t smem_u32(const void* p) {
    uint32_t a;
    asm("{ .reg .u64 t; cvta.to.shared.u64 t, %1; cvt.u32.u64 %0, t; }" : "=r"(a) : "l"(p));
    return a;
}
__device__ __forceinline__ void ldm_x4(uint32_t& r0, uint32_t& r1, uint32_t& r2, uint32_t& r3, uint32_t addr) {
    asm volatile("ldmatrix.sync.aligned.m8n8.x4.shared.b16 {%0,%1,%2,%3}, [%4];"
                 : "=r"(r0), "=r"(r1), "=r"(r2), "=r"(r3) : "r"(addr));
}
__device__ __forceinline__ void mma_f16(float* c, const uint32_t* a, uint32_t b0, uint32_t b1) {
    asm volatile("mma.sync.aligned.m16n8k16.row.col.f32.f16.f16.f32 "
                 "{%0,%1,%2,%3}, {%4,%5,%6,%7}, {%8,%9}, {%0,%1,%2,%3};"
                 : "+f"(c[0]), "+f"(c[1]), "+f"(c[2]), "+f"(c[3])
                 : "r"(a[0]), "r"(a[1]), "r"(a[2]), "r"(a[3]), "r"(b0), "r"(b1));
}
__device__ __forceinline__ void cp16(uint32_t dst, const void* src) {
    asm volatile("cp.async.ca.shared.global [%0], [%1], 16;" :: "r"(dst), "l"(src));
}
#define CP_COMMIT() asm volatile("cp.async.commit_group;" ::: "memory")
#define CP_WAIT0()  asm volatile("cp.async.wait_group 0;" ::: "memory")

// ---------------- 3x3 SAME conv + bias + relu + fused 2x2 maxpool ----------------
template<int IC,int ICC,int OC,int OCB,int OCPT,int H,int W,int TH>
__global__ void conv3x3_pool(const float* __restrict__ in,
                             const float* __restrict__ wgt,
                             const float* __restrict__ bias,
                             float* __restrict__ out)
{
    constexpr int PTH = (TH/2)*(W/2);
    constexpr int BY  = OCB/OCPT;
    constexpr int NT  = PTH*BY;
    constexpr int WP  = W+2;
    constexpr int THP = TH+2;
    __shared__ float s_in[ICC*THP*WP];
    __shared__ float s_w[ICC*OCB*9];

    const int b   = blockIdx.x;
    const int oc0 = blockIdx.y*OCB;
    const int y0  = blockIdx.z*TH;
    const int tx  = threadIdx.x;
    const int ty  = threadIdx.y;
    const int tid = ty*PTH + tx;

    float acc[4][OCPT];
    #pragma unroll
    for (int p=0;p<4;p++)
        #pragma unroll
        for (int o=0;o<OCPT;o++) acc[p][o]=0.f;

    const int ppy = tx/(W/2), ppx = tx%(W/2);
    int ly[4], lx[4];
    #pragma unroll
    for (int p=0;p<4;p++){ ly[p]=2*ppy+(p>>1); lx[p]=2*ppx+(p&1); }

    for (int c0=0;c0<IC;c0+=ICC) {
        __syncthreads();
        for (int idx=tid; idx<ICC*THP*WP; idx+=NT) {
            int ic = idx/(THP*WP); int r = idx - ic*(THP*WP);
            int yy = r/WP, xx = r - yy*WP;
            int gy = y0+yy-1, gx = xx-1;
            float vv=0.f;
            if (gy>=0 && gy<H && gx>=0 && gx<W)
                vv = in[((b*IC + c0+ic)*H + gy)*W + gx];
            s_in[idx]=vv;
        }
        for (int idx=tid; idx<ICC*OCB*9; idx+=NT) {
            int ic = idx/(OCB*9); int r = idx - ic*(OCB*9);
            int oc = r/9, k = r - oc*9;
            s_w[idx] = wgt[((oc0+oc)*IC + c0+ic)*9 + k];
        }
        __syncthreads();
        for (int ic=0; ic<ICC; ic++) {
            #pragma unroll
            for (int k=0;k<9;k++) {
                float wk[OCPT];
                #pragma unroll
                for (int o=0;o<OCPT;o++)
                    wk[o] = s_w[ic*OCB*9 + (ty*OCPT+o)*9 + k];
                #pragma unroll
                for (int p=0;p<4;p++) {
                    float iv = s_in[ic*THP*WP + (ly[p]+k/3)*WP + lx[p]+(k%3)];
                    #pragma unroll
                    for (int o=0;o<OCPT;o++) acc[p][o]=fmaf(iv,wk[o],acc[p][o]);
                }
            }
        }
    }
    #pragma unroll
    for (int o=0;o<OCPT;o++){
        int oc = oc0 + ty*OCPT + o;
        float m = fmaxf(fmaxf(acc[0][o],acc[1][o]), fmaxf(acc[2][o],acc[3][o]));
        out[((b*OC + oc)*(H/2) + (y0>>1)+ppy)*(W/2) + ppx] = fmaxf(m + bias[oc], 0.f);
    }
}

// ---------------- conv3 ic-split: unpooled partials, grid (4,16,4) ----------------
// z = ytile | (icsplit<<1); block (48,4). IC=128 split 2x64, ICC=16, OCB=16, OCPT=4
__global__ void conv3_split_k(const float* __restrict__ in,
                              const float* __restrict__ wgt,
                              float* __restrict__ part)
{
    constexpr int IC=128, ICC=16, OCB=16, OCPT=4, H=16, W=24, TH=8;
    constexpr int PTH=(TH/2)*(W/2);   // 48
    constexpr int NT=PTH*4;           // 192
    constexpr int WP=W+2, THP=TH+2;
    __shared__ float s_in[ICC*THP*WP];
    __shared__ float s_w[ICC*OCB*9];

    const int b   = blockIdx.x;
    const int oc0 = blockIdx.y*OCB;
    const int y0  = (blockIdx.z & 1)*TH;
    const int ic0 = (blockIdx.z >> 1)*64;
    const int s   = blockIdx.z >> 1;
    const int tx  = threadIdx.x;
    const int ty  = threadIdx.y;
    const int tid = ty*PTH + tx;

    float acc[4][OCPT];
    #pragma unroll
    for (int p=0;p<4;p++)
        #pragma unroll
        for (int o=0;o<OCPT;o++) acc[p][o]=0.f;

    const int ppy = tx/(W/2), ppx = tx%(W/2);
    int ly[4], lx[4];
    #pragma unroll
    for (int p=0;p<4;p++){ ly[p]=2*ppy+(p>>1); lx[p]=2*ppx+(p&1); }

    for (int c0=ic0; c0<ic0+64; c0+=ICC) {
        __syncthreads();
        for (int idx=tid; idx<ICC*THP*WP; idx+=NT) {
            int ic = idx/(THP*WP); int r = idx - ic*(THP*WP);
            int yy = r/WP, xx = r - yy*WP;
            int gy = y0+yy-1, gx = xx-1;
            float vv=0.f;
            if (gy>=0 && gy<H && gx>=0 && gx<W)
                vv = in[((b*IC + c0+ic)*H + gy)*W + gx];
            s_in[idx]=vv;
        }
        for (int idx=tid; idx<ICC*OCB*9; idx+=NT) {
            int ic = idx/(OCB*9); int r = idx - ic*(OCB*9);
            int oc = r/9, k = r - oc*9;
            s_w[idx] = wgt[((oc0+oc)*IC + c0+ic)*9 + k];
        }
        __syncthreads();
        for (int ic=0; ic<ICC; ic++) {
            #pragma unroll
            for (int k=0;k<9;k++) {
                float wk[OCPT];
                #pragma unroll
                for (int o=0;o<OCPT;o++)
                    wk[o] = s_w[ic*OCB*9 + (ty*OCPT+o)*9 + k];
                #pragma unroll
                for (int p=0;p<4;p++) {
                    float iv = s_in[ic*THP*WP + (ly[p]+k/3)*WP + lx[p]+(k%3)];
                    #pragma unroll
                    for (int o=0;o<OCPT;o++) acc[p][o]=fmaf(iv,wk[o],acc[p][o]);
                }
            }
        }
    }
    #pragma unroll
    for (int o=0;o<OCPT;o++){
        int oc = oc0 + ty*OCPT + o;
        #pragma unroll
        for (int p=0;p<4;p++)
            part[((s*4 + b)*256 + oc)*384 + (y0+ly[p])*24 + lx[p]] = acc[p][o];
    }
}

// ---------------- conv3 combine: sum splits + bias + relu + pool -> p3 ----------
__global__ void combine3_k(const float* __restrict__ part, const float* __restrict__ bias,
                           float* __restrict__ p3)
{
    int idx = blockIdx.x*256 + threadIdx.x;
    if (idx >= 4*256*96) return;
    int px = idx % 12; int t = idx / 12;
    int py = t % 8;    t /= 8;
    int oc = t % 256;  int b = t / 256;
    const float* p0 = part + ((size_t)(0*4 + b)*256 + oc)*384;
    const float* p1 = part + ((size_t)(1*4 + b)*256 + oc)*384;
    float m = -3.4e38f;
    #pragma unroll
    for (int yy=0; yy<2; yy++)
        #pragma unroll
        for (int xx=0; xx<2; xx++) {
            int off = (2*py+yy)*24 + 2*px+xx;
            m = fmaxf(m, p0[off] + p1[off]);
        }
    p3[((b*256+oc)*8 + py)*12 + px] = fmaxf(m + bias[oc], 0.f);
}

// ---------------- fused prep: w3 fp16 | w2 fp16 | w4 hi/lo | im2col of p3 ----------
__global__ void prep_all_k(const float* __restrict__ w3, const float* __restrict__ w2,
                           const float* __restrict__ w4, const float* __restrict__ p3,
                           __half* __restrict__ w3hi, __half* __restrict__ w2hi,
                           __half* __restrict__ w4hi, __half* __restrict__ w4lo,
                           __half* __restrict__ A)
{
    int idx = blockIdx.x*256 + threadIdx.x;
    if (idx < 256*3072) {
        int k = idx/3072, n = idx - k*3072;
        w3hi[n*256+k] = __float2half(w3[idx]);
    } else if (idx < 256*3072 + 256*256) {
        int i2 = idx - 256*3072;
        int k = i2 >> 8, n = i2 & 255;
        w2hi[n*256+k] = __float2half(w2[i2]);
    } else if (idx < 256*3072 + 256*256 + 512*2304) {
        int i3 = idx - 256*3072 - 256*256;
        float vv = w4[i3];                  // e4w already [oc][ic*9]
        __half h = __float2half(vv);
        w4hi[i3] = h;
        w4lo[i3] = __float2half(vv - __half2float(h));
    } else {
        int i4 = idx - 256*3072 - 256*256 - 512*2304;
        if (i4 >= 4*128*2304) return;
        int c = i4 % 2304; int r = i4 / 2304;
        int b = r >> 7, px = r & 127;
        float v = 0.f;
        if (px < 96) {
            int ic = c/9, k = c - ic*9;
            int y = px/12, x = px - 12*y;
            int gy = y + k/3 - 1, gx = x + (k%3) - 1;
            if (gy>=0 && gy<8 && gx>=0 && gx<12)
                v = p3[((b*256+ic)*8 + gy)*12 + gx];
        }
        A[i4] = __float2half(v);
    }
}

// ---------------- conv4 GEMM: part[ks] = A[b] @ (W4hi+W4lo)^T, K-split x4 ----------
static constexpr int C4_TILE  = 18432;
static constexpr int C4_STAGE = 3*C4_TILE;
static constexpr int C4_DYN   = 2*C4_STAGE;
__global__ void __launch_bounds__(256,1) conv4_mma_k(
    const __half* __restrict__ A,
    const __half* __restrict__ whi, const __half* __restrict__ wlo,
    float* __restrict__ part)
{
    extern __shared__ __align__(16) char dsm[];
    const int tid  = threadIdx.x;
    const int wid  = tid >> 5;
    const int lane = tid & 31;
    const int wm   = wid >> 1;
    const int wn   = wid & 1;
    const int b    = blockIdx.x;
    const int nt0  = blockIdx.y;
    const int ks   = blockIdx.z;

    const __half* Aa = A   + (size_t)(b*128)*2304   + ks*576;
    const __half* Bh = whi + (size_t)(nt0*128)*2304 + ks*576;
    const __half* Bl = wlo + (size_t)(nt0*128)*2304 + ks*576;
    const uint32_t dsb = smem_u32(dsm);

    float c[2][8][4];
    #pragma unroll
    for (int mt=0;mt<2;mt++)
        #pragma unroll
        for (int nt=0;nt<8;nt++)
            #pragma unroll
            for (int e=0;e<4;e++) c[mt][nt][e]=0.f;

    auto issue = [&](int cn, int stage) {
        const int koff = cn*64;
        const uint32_t dA = dsb + stage*C4_STAGE;
        const uint32_t dH = dA + C4_TILE;
        const uint32_t dL = dH + C4_TILE;
        #pragma unroll
        for (int i2=0;i2<4;i2++){
            int cidx = tid + i2*256;
            int row = cidx >> 3, g = cidx & 7;
            cp16(dA + row*144 + g*16, Aa + (size_t)row*2304 + koff + g*8);
            cp16(dH + row*144 + g*16, Bh + (size_t)row*2304 + koff + g*8);
            cp16(dL + row*144 + g*16, Bl + (size_t)row*2304 + koff + g*8);
        }
        CP_COMMIT();
    };

    issue(0, 0);

    for (int ch = 0; ch < 9; ch++) {
        CP_WAIT0();
        __syncthreads();
        if (ch < 8) issue(ch+1, (ch+1)&1);

        const uint32_t sAb = dsb + (ch&1)*C4_STAGE;
        const uint32_t sH  = sAb + C4_TILE;
        const uint32_t sL  = sH + C4_TILE;
        #pragma unroll
        for (int kstep=0; kstep<4; kstep++) {
            uint32_t a[2][4];
            #pragma unroll
            for (int mt=0; mt<2; mt++) {
                int row = wm*32 + mt*16 + (lane&7) + ((lane>>3)&1)*8;
                int col = ((lane>>4)&1)*8 + kstep*16;
                ldm_x4(a[mt][0],a[mt][1],a[mt][2],a[mt][3], sAb + (row*72 + col)*2);
            }
            #pragma unroll
            for (int ntp=0; ntp<4; ntp++) {
                int rn = wn*64 + ntp*16 + (lane&7) + ((lane>>4)&1)*8;
                int ck = ((lane>>3)&1)*8 + kstep*16;
                uint32_t r0,r1,r2,r3;
                ldm_x4(r0,r1,r2,r3, sH + (rn*72 + ck)*2);
                mma_f16(c[0][2*ntp],   a[0], r0, r1);
                mma_f16(c[0][2*ntp+1], a[0], r2, r3);
                mma_f16(c[1][2*ntp],   a[1], r0, r1);
                mma_f16(c[1][2*ntp+1], a[1], r2, r3);
                ldm_x4(r0,r1,r2,r3, sL + (rn*72 + ck)*2);
                mma_f16(c[0][2*ntp],   a[0], r0, r1);
                mma_f16(c[0][2*ntp+1], a[0], r2, r3);
                mma_f16(c[1][2*ntp],   a[1], r0, r1);
                mma_f16(c[1][2*ntp+1], a[1], r2, r3);
            }
        }
        __syncthreads();
    }

    #pragma unroll
    for (int mt=0; mt<2; mt++) {
        int row = wm*32 + mt*16 + (lane>>2);
        #pragma unroll
        for (int nt=0; nt<8; nt++) {
            int col = nt0*128 + wn*64 + nt*8 + (lane&3)*2;
            size_t base = ((size_t)(ks*4 + b)*512 + col)*96;
            if (row < 96) {
                part[base + row]      = c[mt][nt][0];
                part[base + 96 + row] = c[mt][nt][1];
            }
            if (row + 8 < 96) {
                part[base + row + 8]      = c[mt][nt][2];
                part[base + 96 + row + 8] = c[mt][nt][3];
            }
        }
    }
}

// ---------------- u,v = F @ A, F @ B ; blockIdx.y==16 -> ws ----------------
__global__ void __launch_bounds__(256) uvws_k(const float* __restrict__ cpart,
                                              const float* __restrict__ e4b,
                                              const float* __restrict__ g1w,
                                              const float* __restrict__ g1b,
                                              const float* __restrict__ sen,
                                              float* __restrict__ u, float* __restrict__ v,
                                              float* __restrict__ ws)
{
    __shared__ float sF[128*96];
    const int b  = blockIdx.x;
    const int tid = threadIdx.x;
    const int PS = 4*512*96;

    if (blockIdx.y == 16) {
        float* ss = sF;
        const int n = tid;
        for (int k=n;k<384;k+=256) ss[k]=sen[b*384+k];
        __syncthreads();
        float acc = g1b[n];
        for (int k=0;k<384;k++) acc = fmaf(ss[k], g1w[(1028+k)*256+n], acc);
        ws[b*256+n]=acc;
        return;
    }

    const int n0 = blockIdx.y*16;
    const int n  = tid & 15;
    const int pg = tid >> 4;           // 0..15, 6 rows each
    float au[6], av[6];
    #pragma unroll
    for (int i=0;i<6;i++){ au[i]=0.f; av[i]=0.f; }

    for (int k0=0; k0<512; k0+=128) {
        __syncthreads();
        for (int idx=tid; idx<128*96; idx+=256) {
            int kk = idx/96, p = idx - kk*96;
            int base = (b*512 + k0 + kk)*96 + p;
            float vv = cpart[base] + cpart[base+PS] + cpart[base+2*PS] + cpart[base+3*PS]
                     + e4b[k0+kk];
            sF[kk*96 + p] = fmaxf(vv, 0.f);
        }
        __syncthreads();
        for (int kk=0; kk<128; kk++) {
            float wu = g1w[(k0+kk)*256 + n0 + n];
            float wv = g1w[(514 + k0+kk)*256 + n0 + n];
            const float* fr = &sF[kk*96 + pg*6];
            #pragma unroll
            for (int i=0;i<6;i++){
                float f = fr[i];
                au[i] = fmaf(f, wu, au[i]);
                av[i] = fmaf(f, wv, av[i]);
            }
        }
    }
    {
        float wu0 = g1w[512*256 + n0 + n], wu1 = g1w[513*256 + n0 + n];
        float wv0 = g1w[(514+512)*256 + n0 + n], wv1 = g1w[(514+513)*256 + n0 + n];
        #pragma unroll
        for (int i=0;i<6;i++){
            int p = pg*6 + i;
            float fx = -1.f + (2.f*(float)(p/8))/11.f;
            float fy = -1.f + (2.f*(float)(p%8))/7.f;
            au[i] += fx*wu0 + fy*wu1;
            av[i] += fx*wv0 + fy*wv1;
        }
    }
    #pragma unroll
    for (int i=0;i<6;i++){
        int p = pg*6 + i;
        u[(b*96+p)*256 + n0 + n] = au[i];
        v[(b*96+p)*256 + n0 + n] = av[i];
    }
}

// ---------------- h2 = relu(h1 @ W2 + b2) -> fp16, single-pass mma ----------------
static constexpr int H2_DYN = 30720;   // A 10240 + B 2 stages x 10240
__global__ void __launch_bounds__(256,2) h2_mma_k(
    const float* __restrict__ u, const float* __restrict__ v,
    const float* __restrict__ ws,
    const __half* __restrict__ w2thi,
    const float* __restrict__ b2, __half* __restrict__ a16)
{
    extern __shared__ __align__(16) char dsm[];
    __half* sA = (__half*)dsm;                       // 128*40
    __shared__ float sws[256];
    __shared__ float sb2[128];

    const int tid = threadIdx.x;
    const int wid = tid >> 5, lane = tid & 31;
    const int wm = wid >> 1, wn = wid & 1;
    const int r0 = blockIdx.x*128;
    const int n0 = blockIdx.y*128;
    const int b  = r0/9216;

    sws[tid] = ws[b*256 + tid];
    if (tid < 128) sb2[tid] = b2[n0 + tid];

    const int arow = tid >> 1;
    const int kh   = (tid & 1)*16;
    const int rr   = (r0 + arow) - b*9216;
    const int ii   = rr/96, jj = rr - ii*96;
    const float* up = u + (b*96 + jj)*256 + kh;
    const float* vp = v + (b*96 + ii)*256 + kh;

    const __half* Wh = w2thi + n0*256;
    const uint32_t dsb = smem_u32(dsm);

    auto issueB = [&](int cn, int stage) {
        const int koff = cn*32;
        const uint32_t dH = dsb + 10240 + stage*10240;
        #pragma unroll
        for (int i2=0;i2<2;i2++){
            int cidx = tid + i2*256;
            int row = cidx >> 2, g = cidx & 3;
            cp16(dH + row*80 + g*16, Wh + row*256 + koff + g*8);
        }
        CP_COMMIT();
    };

    float c[2][8][4];
    #pragma unroll
    for (int mt=0;mt<2;mt++)
        #pragma unroll
        for (int nt=0;nt<8;nt++)
            #pragma unroll
            for (int e=0;e<4;e++) c[mt][nt][e]=0.f;

    issueB(0, 0);

    for (int ch = 0; ch < 8; ch++) {
        CP_WAIT0();
        __syncthreads();
        {
            const int koff = ch*32;
            float uf[16], vf[16];
            #pragma unroll
            for (int q=0;q<4;q++){
                *(float4*)&uf[q*4] = *(const float4*)(up + koff + q*4);
                *(float4*)&vf[q*4] = *(const float4*)(vp + koff + q*4);
            }
            __half hv[16];
            const float* wsp = &sws[koff + kh];
            #pragma unroll
            for (int e=0;e<16;e++) hv[e] = __float2half(fmaxf(uf[e]+vf[e]+wsp[e], 0.f));
            *(uint4*)&sA[arow*40 + kh]     = *(const uint4*)hv;
            *(uint4*)&sA[arow*40 + kh + 8] = *(const uint4*)(hv+8);
        }
        if (ch < 7) issueB(ch+1, (ch+1)&1);
        __syncthreads();

        const uint32_t sAb = dsb;
        const uint32_t sH = dsb + 10240 + (ch&1)*10240;
        #pragma unroll
        for (int ks=0; ks<2; ks++) {
            uint32_t a[2][4];
            #pragma unroll
            for (int mt=0; mt<2; mt++) {
                int row = wm*32 + mt*16 + (lane&7) + ((lane>>3)&1)*8;
                int col = ((lane>>4)&1)*8 + ks*16;
                ldm_x4(a[mt][0],a[mt][1],a[mt][2],a[mt][3], sAb + (row*40 + col)*2);
            }
            #pragma unroll
            for (int ntp=0; ntp<4; ntp++) {
                int rn = wn*64 + ntp*16 + (lane&7) + ((lane>>4)&1)*8;
                int ck = ((lane>>3)&1)*8 + ks*16;
                uint32_t r0r,r1r,r2r,r3r;
                ldm_x4(r0r,r1r,r2r,r3r, sH + (rn*40 + ck)*2);
                mma_f16(c[0][2*ntp],   a[0], r0r, r1r);
                mma_f16(c[0][2*ntp+1], a[0], r2r, r3r);
                mma_f16(c[1][2*ntp],   a[1], r0r, r1r);
                mma_f16(c[1][2*ntp+1], a[1], r2r, r3r);
            }
        }
    }

    #pragma unroll
    for (int mt=0; mt<2; mt++) {
        int row_l = r0 + wm*32 + mt*16 + (lane>>2);
        #pragma unroll
        for (int nt=0; nt<8; nt++) {
            int col = n0 + wn*64 + nt*8 + (lane&3)*2;
            float b0 = sb2[col - n0], b1 = sb2[col - n0 + 1];
            __half2 lo2 = __floats2half2_rn(fmaxf(c[mt][nt][0]+b0,0.f), fmaxf(c[mt][nt][1]+b1,0.f));
            __half2 hi2 = __floats2half2_rn(fmaxf(c[mt][nt][2]+b0,0.f), fmaxf(c[mt][nt][3]+b1,0.f));
            *(__half2*)&a16[(size_t)row_l*256 + col]     = lo2;
            *(__half2*)&a16[(size_t)(row_l+8)*256 + col] = hi2;
        }
    }
}

// ---------------- g3: single fp16 pass, BK=64 (4 fat chunks), 2-stage cp.async ----
static constexpr int G3_TILE  = 18432;
static constexpr int G3_STAGE = 2*G3_TILE;
static constexpr int G3_DYN   = 2*G3_STAGE;
__global__ void __launch_bounds__(256,2) g3_mma_k(
    const __half* __restrict__ a16,
    const __half* __restrict__ wthi,
    const float* __restrict__ b3, float* __restrict__ part)
{
    extern __shared__ __align__(16) char dsm[];
    __shared__ float sbias[128];
    __shared__ float spart[4][128];

    const int tid  = threadIdx.x;
    const int wid  = tid >> 5;
    const int lane = tid & 31;
    const int wm   = wid >> 1;
    const int wn   = wid & 1;
    const int mtile = blockIdx.x;
    const int ntile = blockIdx.y;

    if (tid < 128) sbias[tid] = b3[ntile*128 + tid];

    const __half* Aa = a16  + (size_t)mtile*128*256;
    const __half* Wh = wthi + (size_t)ntile*128*256;
    const uint32_t dsb = smem_u32(dsm);

    float c[2][8][4];
    #pragma unroll
    for (int mt=0;mt<2;mt++)
        #pragma unroll
        for (int nt=0;nt<8;nt++)
            #pragma unroll
            for (int e=0;e<4;e++) c[mt][nt][e]=0.f;

    auto issue = [&](int cn, int stage) {
        const int koff = cn*64;
        const uint32_t dA = dsb + stage*G3_STAGE;
        const uint32_t dB = dA + G3_TILE;
        #pragma unroll
        for (int i2=0;i2<4;i2++){
            int cidx = tid + i2*256;
            int row = cidx >> 3, g = cidx & 7;
            cp16(dA + row*144 + g*16, Aa + row*256 + koff + g*8);
            cp16(dB + row*144 + g*16, Wh + row*256 + koff + g*8);
        }
        CP_COMMIT();
    };

    issue(0, 0);

    for (int ch = 0; ch < 4; ch++) {
        CP_WAIT0();
        __syncthreads();
        if (ch < 3) issue(ch+1, (ch+1)&1);

        const uint32_t sAb = dsb + (ch&1)*G3_STAGE;
        const uint32_t sB  = sAb + G3_TILE;
        #pragma unroll
        for (int ks=0; ks<4; ks++) {
            uint32_t a[2][4];
            #pragma unroll
            for (int mt=0; mt<2; mt++) {
                int row = wm*32 + mt*16 + (lane&7) + ((lane>>3)&1)*8;
                int col = ((lane>>4)&1)*8 + ks*16;
                ldm_x4(a[mt][0],a[mt][1],a[mt][2],a[mt][3], sAb + (row*72 + col)*2);
            }
            #pragma unroll
            for (int ntp=0; ntp<4; ntp++) {
                int rn = wn*64 + ntp*16 + (lane&7) + ((lane>>4)&1)*8;
                int ck = ((lane>>3)&1)*8 + ks*16;
                uint32_t r0,r1,r2,r3;
                ldm_x4(r0,r1,r2,r3, sB + (rn*72 + ck)*2);
                mma_f16(c[0][2*ntp],   a[0], r0, r1);
                mma_f16(c[0][2*ntp+1], a[0], r2, r3);
                mma_f16(c[1][2*ntp],   a[1], r0, r1);
                mma_f16(c[1][2*ntp+1], a[1], r2, r3);
            }
        }
        __syncthreads();
    }

    #pragma unroll
    for (int nt=0; nt<8; nt++) {
        int ncol = wn*64 + nt*8 + (lane&3)*2;
        float bias0 = sbias[ncol];
        float bias1 = sbias[ncol+1];
        float t0 = 0.f, t1 = 0.f;
        #pragma unroll
        for (int mt=0; mt<2; mt++) {
            t0 += fmaxf(c[mt][nt][0] + bias0, 0.f) + fmaxf(c[mt][nt][2] + bias0, 0.f);
            t1 += fmaxf(c[mt][nt][1] + bias1, 0.f) + fmaxf(c[mt][nt][3] + bias1, 0.f);
        }
        t0 += __shfl_xor_sync(0xFFFFFFFFu, t0, 4);
        t0 += __shfl_xor_sync(0xFFFFFFFFu, t0, 8);
        t0 += __shfl_xor_sync(0xFFFFFFFFu, t0, 16);
        t1 += __shfl_xor_sync(0xFFFFFFFFu, t1, 4);
        t1 += __shfl_xor_sync(0xFFFFFFFFu, t1, 8);
        t1 += __shfl_xor_sync(0xFFFFFFFFu, t1, 16);
        if (lane < 4) {
            spart[wm][wn*64 + nt*8 + lane*2]     = t0;
            spart[wm][wn*64 + nt*8 + lane*2 + 1] = t1;
        }
    }
    __syncthreads();
    if (tid < 128) {
        float s = spart[0][tid] + spart[1][tid] + spart[2][tid] + spart[3][tid];
        part[(size_t)mtile*3072 + ntile*128 + tid] = s;
    }
}

// ---------------- final reduce over 72 row-tiles per batch ----------------
__global__ void final_reduce_k(const float* __restrict__ part, float* __restrict__ outp)
{
    int idx = blockIdx.x*blockDim.x + threadIdx.x;
    if (idx >= 4*3072) return;
    int b = idx/3072, n = idx - b*3072;
    float s = 0.f;
    for (int t=0;t<72;t++) s += part[(b*72+t)*3072 + n];
    outp[idx] = s;
}

// ---------------- launch ----------------
extern "C" void kernel_launch(void* const* d_in, const int* in_sizes, int n_in,
                              void* d_out, int out_size)
{
    const float* x      = (const float*)d_in[0];
    const float* sen    = (const float*)d_in[1];
    const float* e1w    = (const float*)d_in[2];
    const float* e1b    = (const float*)d_in[3];
    const float* e2w    = (const float*)d_in[4];
    const float* e2b    = (const float*)d_in[5];
    const float* e3w    = (const float*)d_in[6];
    const float* e3b    = (const float*)d_in[7];
    const float* e4w    = (const float*)d_in[8];
    const float* e4b    = (const float*)d_in[9];
    const float* g1w    = (const float*)d_in[10];
    const float* g1b    = (const float*)d_in[11];
    const float* g2w    = (const float*)d_in[12];
    const float* g2b    = (const float*)d_in[13];
    const float* g3w    = (const float*)d_in[14];
    const float* g3b    = (const float*)d_in[15];
    float* outp = (float*)d_out;

    float *pp1,*pp2,*pc3,*pp3,*pcpart,*pu,*pv,*pws,*ppart;
    __half *pa4,*pw4hi,*pw4lo,*pa16,*pwthi,*pw2thi;
    cudaGetSymbolAddress((void**)&pp1,  g_p1);
    cudaGetSymbolAddress((void**)&pp2,  g_p2);
    cudaGetSymbolAddress((void**)&pc3,  g_c3part);
    cudaGetSymbolAddress((void**)&pp3,  g_p3);
    cudaGetSymbolAddress((void**)&pa4,  g_a4);
    cudaGetSymbolAddress((void**)&pw4hi,g_w4hi);
    cudaGetSymbolAddress((void**)&pw4lo,g_w4lo);
    cudaGetSymbolAddress((void**)&pcpart,g_cpart);
    cudaGetSymbolAddress((void**)&pu,   g_u);
    cudaGetSymbolAddress((void**)&pv,   g_v);
    cudaGetSymbolAddress((void**)&pws,  g_ws);
    cudaGetSymbolAddress((void**)&pa16, g_a16);
    cudaGetSymbolAddress((void**)&pwthi,g_wthi);
    cudaGetSymbolAddress((void**)&pw2thi,g_w2thi);
    cudaGetSymbolAddress((void**)&ppart,g_part);

    cudaFuncSetAttribute(h2_mma_k, cudaFuncAttributeMaxDynamicSharedMemorySize, H2_DYN);
    cudaFuncSetAttribute(g3_mma_k, cudaFuncAttributeMaxDynamicSharedMemorySize, G3_DYN);
    cudaFuncSetAttribute(conv4_mma_k, cudaFuncAttributeMaxDynamicSharedMemorySize, C4_DYN);

    // encoder
    conv3x3_pool<3,3,64,32,8,64,96,4><<<dim3(4,2,16), dim3(96,4)>>>(x, e1w, e1b, pp1);
    conv3x3_pool<64,16,128,16,4,32,48,4><<<dim3(4,8,8), dim3(48,4)>>>(pp1, e2w, e2b, pp2);
    conv3_split_k<<<dim3(4,16,4), dim3(48,4)>>>(pp2, e3w, pc3);
    combine3_k<<<(4*256*96+255)/256,256>>>(pc3, e3b, pp3);
    prep_all_k<<<(256*3072+256*256+512*2304+4*128*2304+255)/256,256>>>(
        g3w, g2w, e4w, pp3, pwthi, pw2thi, pw4hi, pw4lo, pa4);
    conv4_mma_k<<<dim3(4,4,4),256,C4_DYN>>>(pa4, pw4hi, pw4lo, pcpart);

    // relation net
    uvws_k<<<dim3(4,17),256>>>(pcpart, e4b, g1w, g1b, sen, pu, pv, pws);
    h2_mma_k<<<dim3(288,2),256,H2_DYN>>>(pu, pv, pws, pw2thi, g2b, pa16);
    g3_mma_k<<<dim3(288,24),256,G3_DYN>>>(pa16, pwthi, g3b, ppart);
    final_reduce_k<<<48,256>>>(ppart, outp);
}

// round 16
// speedup vs baseline: 1.2843x; 1.0184x over previous
#include <cuda_runtime.h>
#include <cuda_fp16.h>
#include <cstdint>
#include <cstddef>

// ---------------- scratch (__device__ globals; no allocations) ----------------
__device__ float g_p1[4*64*32*48];
__device__ float g_p2[4*128*16*24];
__device__ float g_c3part[2*4*256*384];
__device__ float g_p3[4*256*8*12];
__device__ __half g_a4[4*128*2304];
__device__ __half g_w4hi[512*2304];
__device__ __half g_w4lo[512*2304];
__device__ float g_cpart[4*4*512*96];
__device__ float g_u[4*96*256];
__device__ float g_v[4*96*256];
__device__ float g_ws[4*256];
__device__ __half g_a16[36864*256];
__device__ __half g_wthi[3072*256];
__device__ __half g_w2thi[256*256];
__device__ float g_part[288*3072];

// ---------------- helpers ----------------
__device__ __forceinline__ uint32_t smem_u32(const void* p) {
    uint32_t a;
    asm("{ .reg .u64 t; cvta.to.shared.u64 t, %1; cvt.u32.u64 %0, t; }" : "=r"(a) : "l"(p));
    return a;
}
__device__ __forceinline__ void ldm_x4(uint32_t& r0, uint32_t& r1, uint32_t& r2, uint32_t& r3, uint32_t addr) {
    asm volatile("ldmatrix.sync.aligned.m8n8.x4.shared.b16 {%0,%1,%2,%3}, [%4];"
                 : "=r"(r0), "=r"(r1), "=r"(r2), "=r"(r3) : "r"(addr));
}
__device__ __forceinline__ void mma_f16(float* c, const uint32_t* a, uint32_t b0, uint32_t b1) {
    asm volatile("mma.sync.aligned.m16n8k16.row.col.f32.f16.f16.f32 "
                 "{%0,%1,%2,%3}, {%4,%5,%6,%7}, {%8,%9}, {%0,%1,%2,%3};"
                 : "+f"(c[0]), "+f"(c[1]), "+f"(c[2]), "+f"(c[3])
                 : "r"(a[0]), "r"(a[1]), "r"(a[2]), "r"(a[3]), "r"(b0), "r"(b1));
}
__device__ __forceinline__ void cp16(uint32_t dst, const void* src) {
    asm volatile("cp.async.ca.shared.global [%0], [%1], 16;" :: "r"(dst), "l"(src));
}
#define CP_COMMIT() asm volatile("cp.async.commit_group;" ::: "memory")
#define CP_WAIT0()  asm volatile("cp.async.wait_group 0;" ::: "memory")
#define CP_WAIT1()  asm volatile("cp.async.wait_group 1;" ::: "memory")

// ---------------- 3x3 SAME conv + bias + relu + fused 2x2 maxpool ----------------
template<int IC,int ICC,int OC,int OCB,int OCPT,int H,int W,int TH>
__global__ void conv3x3_pool(const float* __restrict__ in,
                             const float* __restrict__ wgt,
                             const float* __restrict__ bias,
                             float* __restrict__ out)
{
    constexpr int PTH = (TH/2)*(W/2);
    constexpr int BY  = OCB/OCPT;
    constexpr int NT  = PTH*BY;
    constexpr int WP  = W+2;
    constexpr int THP = TH+2;
    __shared__ float s_in[ICC*THP*WP];
    __shared__ float s_w[ICC*OCB*9];

    const int b   = blockIdx.x;
    const int oc0 = blockIdx.y*OCB;
    const int y0  = blockIdx.z*TH;
    const int tx  = threadIdx.x;
    const int ty  = threadIdx.y;
    const int tid = ty*PTH + tx;

    float acc[4][OCPT];
    #pragma unroll
    for (int p=0;p<4;p++)
        #pragma unroll
        for (int o=0;o<OCPT;o++) acc[p][o]=0.f;

    const int ppy = tx/(W/2), ppx = tx%(W/2);
    int ly[4], lx[4];
    #pragma unroll
    for (int p=0;p<4;p++){ ly[p]=2*ppy+(p>>1); lx[p]=2*ppx+(p&1); }

    for (int c0=0;c0<IC;c0+=ICC) {
        __syncthreads();
        for (int idx=tid; idx<ICC*THP*WP; idx+=NT) {
            int ic = idx/(THP*WP); int r = idx - ic*(THP*WP);
            int yy = r/WP, xx = r - yy*WP;
            int gy = y0+yy-1, gx = xx-1;
            float vv=0.f;
            if (gy>=0 && gy<H && gx>=0 && gx<W)
                vv = in[((b*IC + c0+ic)*H + gy)*W + gx];
            s_in[idx]=vv;
        }
        for (int idx=tid; idx<ICC*OCB*9; idx+=NT) {
            int ic = idx/(OCB*9); int r = idx - ic*(OCB*9);
            int oc = r/9, k = r - oc*9;
            s_w[idx] = wgt[((oc0+oc)*IC + c0+ic)*9 + k];
        }
        __syncthreads();
        for (int ic=0; ic<ICC; ic++) {
            #pragma unroll
            for (int k=0;k<9;k++) {
                float wk[OCPT];
                #pragma unroll
                for (int o=0;o<OCPT;o++)
                    wk[o] = s_w[ic*OCB*9 + (ty*OCPT+o)*9 + k];
                #pragma unroll
                for (int p=0;p<4;p++) {
                    float iv = s_in[ic*THP*WP + (ly[p]+k/3)*WP + lx[p]+(k%3)];
                    #pragma unroll
                    for (int o=0;o<OCPT;o++) acc[p][o]=fmaf(iv,wk[o],acc[p][o]);
                }
            }
        }
    }
    #pragma unroll
    for (int o=0;o<OCPT;o++){
        int oc = oc0 + ty*OCPT + o;
        float m = fmaxf(fmaxf(acc[0][o],acc[1][o]), fmaxf(acc[2][o],acc[3][o]));
        out[((b*OC + oc)*(H/2) + (y0>>1)+ppy)*(W/2) + ppx] = fmaxf(m + bias[oc], 0.f);
    }
}

// ---------------- conv3 ic-split ----------------
__global__ void conv3_split_k(const float* __restrict__ in,
                              const float* __restrict__ wgt,
                              float* __restrict__ part)
{
    constexpr int IC=128, ICC=16, OCB=16, OCPT=4, H=16, W=24, TH=8;
    constexpr int PTH=(TH/2)*(W/2);
    constexpr int NT=PTH*4;
    constexpr int WP=W+2, THP=TH+2;
    __shared__ float s_in[ICC*THP*WP];
    __shared__ float s_w[ICC*OCB*9];

    const int b   = blockIdx.x;
    const int oc0 = blockIdx.y*OCB;
    const int y0  = (blockIdx.z & 1)*TH;
    const int ic0 = (blockIdx.z >> 1)*64;
    const int s   = blockIdx.z >> 1;
    const int tx  = threadIdx.x;
    const int ty  = threadIdx.y;
    const int tid = ty*PTH + tx;

    float acc[4][OCPT];
    #pragma unroll
    for (int p=0;p<4;p++)
        #pragma unroll
        for (int o=0;o<OCPT;o++) acc[p][o]=0.f;

    const int ppy = tx/(W/2), ppx = tx%(W/2);
    int ly[4], lx[4];
    #pragma unroll
    for (int p=0;p<4;p++){ ly[p]=2*ppy+(p>>1); lx[p]=2*ppx+(p&1); }

    for (int c0=ic0; c0<ic0+64; c0+=ICC) {
        __syncthreads();
        for (int idx=tid; idx<ICC*THP*WP; idx+=NT) {
            int ic = idx/(THP*WP); int r = idx - ic*(THP*WP);
            int yy = r/WP, xx = r - yy*WP;
            int gy = y0+yy-1, gx = xx-1;
            float vv=0.f;
            if (gy>=0 && gy<H && gx>=0 && gx<W)
                vv = in[((b*IC + c0+ic)*H + gy)*W + gx];
            s_in[idx]=vv;
        }
        for (int idx=tid; idx<ICC*OCB*9; idx+=NT) {
            int ic = idx/(OCB*9); int r = idx - ic*(OCB*9);
            int oc = r/9, k = r - oc*9;
            s_w[idx] = wgt[((oc0+oc)*IC + c0+ic)*9 + k];
        }
        __syncthreads();
        for (int ic=0; ic<ICC; ic++) {
            #pragma unroll
            for (int k=0;k<9;k++) {
                float wk[OCPT];
                #pragma unroll
                for (int o=0;o<OCPT;o++)
                    wk[o] = s_w[ic*OCB*9 + (ty*OCPT+o)*9 + k];
                #pragma unroll
                for (int p=0;p<4;p++) {
                    float iv = s_in[ic*THP*WP + (ly[p]+k/3)*WP + lx[p]+(k%3)];
                    #pragma unroll
                    for (int o=0;o<OCPT;o++) acc[p][o]=fmaf(iv,wk[o],acc[p][o]);
                }
            }
        }
    }
    #pragma unroll
    for (int o=0;o<OCPT;o++){
        int oc = oc0 + ty*OCPT + o;
        #pragma unroll
        for (int p=0;p<4;p++)
            part[((s*4 + b)*256 + oc)*384 + (y0+ly[p])*24 + lx[p]] = acc[p][o];
    }
}

// ---------------- conv3 combine ----------------
__global__ void combine3_k(const float* __restrict__ part, const float* __restrict__ bias,
                           float* __restrict__ p3)
{
    int idx = blockIdx.x*256 + threadIdx.x;
    if (idx >= 4*256*96) return;
    int px = idx % 12; int t = idx / 12;
    int py = t % 8;    t /= 8;
    int oc = t % 256;  int b = t / 256;
    const float* p0 = part + ((size_t)(0*4 + b)*256 + oc)*384;
    const float* p1 = part + ((size_t)(1*4 + b)*256 + oc)*384;
    float m = -3.4e38f;
    #pragma unroll
    for (int yy=0; yy<2; yy++)
        #pragma unroll
        for (int xx=0; xx<2; xx++) {
            int off = (2*py+yy)*24 + 2*px+xx;
            m = fmaxf(m, p0[off] + p1[off]);
        }
    p3[((b*256+oc)*8 + py)*12 + px] = fmaxf(m + bias[oc], 0.f);
}

// ---------------- fused prep ----------------
__global__ void prep_all_k(const float* __restrict__ w3, const float* __restrict__ w2,
                           const float* __restrict__ w4, const float* __restrict__ p3,
                           __half* __restrict__ w3hi, __half* __restrict__ w2hi,
                           __half* __restrict__ w4hi, __half* __restrict__ w4lo,
                           __half* __restrict__ A)
{
    int idx = blockIdx.x*256 + threadIdx.x;
    if (idx < 256*3072) {
        int k = idx/3072, n = idx - k*3072;
        w3hi[n*256+k] = __float2half(w3[idx]);
    } else if (idx < 256*3072 + 256*256) {
        int i2 = idx - 256*3072;
        int k = i2 >> 8, n = i2 & 255;
        w2hi[n*256+k] = __float2half(w2[i2]);
    } else if (idx < 256*3072 + 256*256 + 512*2304) {
        int i3 = idx - 256*3072 - 256*256;
        float vv = w4[i3];
        __half h = __float2half(vv);
        w4hi[i3] = h;
        w4lo[i3] = __float2half(vv - __half2float(h));
    } else {
        int i4 = idx - 256*3072 - 256*256 - 512*2304;
        if (i4 >= 4*128*2304) return;
        int c = i4 % 2304; int r = i4 / 2304;
        int b = r >> 7, px = r & 127;
        float v = 0.f;
        if (px < 96) {
            int ic = c/9, k = c - ic*9;
            int y = px/12, x = px - 12*y;
            int gy = y + k/3 - 1, gx = x + (k%3) - 1;
            if (gy>=0 && gy<8 && gx>=0 && gx<12)
                v = p3[((b*256+ic)*8 + gy)*12 + gx];
        }
        A[i4] = __float2half(v);
    }
}

// ---------------- conv4 GEMM ----------------
static constexpr int C4_TILE  = 18432;
static constexpr int C4_STAGE = 3*C4_TILE;
static constexpr int C4_DYN   = 2*C4_STAGE;
__global__ void __launch_bounds__(256,1) conv4_mma_k(
    const __half* __restrict__ A,
    const __half* __restrict__ whi, const __half* __restrict__ wlo,
    float* __restrict__ part)
{
    extern __shared__ __align__(16) char dsm[];
    const int tid  = threadIdx.x;
    const int wid  = tid >> 5;
    const int lane = tid & 31;
    const int wm   = wid >> 1;
    const int wn   = wid & 1;
    const int b    = blockIdx.x;
    const int nt0  = blockIdx.y;
    const int ks   = blockIdx.z;

    const __half* Aa = A   + (size_t)(b*128)*2304   + ks*576;
    const __half* Bh = whi + (size_t)(nt0*128)*2304 + ks*576;
    const __half* Bl = wlo + (size_t)(nt0*128)*2304 + ks*576;
    const uint32_t dsb = smem_u32(dsm);

    float c[2][8][4];
    #pragma unroll
    for (int mt=0;mt<2;mt++)
        #pragma unroll
        for (int nt=0;nt<8;nt++)
            #pragma unroll
            for (int e=0;e<4;e++) c[mt][nt][e]=0.f;

    auto issue = [&](int cn, int stage) {
        const int koff = cn*64;
        const uint32_t dA = dsb + stage*C4_STAGE;
        const uint32_t dH = dA + C4_TILE;
        const uint32_t dL = dH + C4_TILE;
        #pragma unroll
        for (int i2=0;i2<4;i2++){
            int cidx = tid + i2*256;
            int row = cidx >> 3, g = cidx & 7;
            cp16(dA + row*144 + g*16, Aa + (size_t)row*2304 + koff + g*8);
            cp16(dH + row*144 + g*16, Bh + (size_t)row*2304 + koff + g*8);
            cp16(dL + row*144 + g*16, Bl + (size_t)row*2304 + koff + g*8);
        }
        CP_COMMIT();
    };

    issue(0, 0);

    for (int ch = 0; ch < 9; ch++) {
        CP_WAIT0();
        __syncthreads();
        if (ch < 8) issue(ch+1, (ch+1)&1);

        const uint32_t sAb = dsb + (ch&1)*C4_STAGE;
        const uint32_t sH  = sAb + C4_TILE;
        const uint32_t sL  = sH + C4_TILE;
        #pragma unroll
        for (int kstep=0; kstep<4; kstep++) {
            uint32_t a[2][4];
            #pragma unroll
            for (int mt=0; mt<2; mt++) {
                int row = wm*32 + mt*16 + (lane&7) + ((lane>>3)&1)*8;
                int col = ((lane>>4)&1)*8 + kstep*16;
                ldm_x4(a[mt][0],a[mt][1],a[mt][2],a[mt][3], sAb + (row*72 + col)*2);
            }
            #pragma unroll
            for (int ntp=0; ntp<4; ntp++) {
                int rn = wn*64 + ntp*16 + (lane&7) + ((lane>>4)&1)*8;
                int ck = ((lane>>3)&1)*8 + kstep*16;
                uint32_t r0,r1,r2,r3;
                ldm_x4(r0,r1,r2,r3, sH + (rn*72 + ck)*2);
                mma_f16(c[0][2*ntp],   a[0], r0, r1);
                mma_f16(c[0][2*ntp+1], a[0], r2, r3);
                mma_f16(c[1][2*ntp],   a[1], r0, r1);
                mma_f16(c[1][2*ntp+1], a[1], r2, r3);
                ldm_x4(r0,r1,r2,r3, sL + (rn*72 + ck)*2);
                mma_f16(c[0][2*ntp],   a[0], r0, r1);
                mma_f16(c[0][2*ntp+1], a[0], r2, r3);
                mma_f16(c[1][2*ntp],   a[1], r0, r1);
                mma_f16(c[1][2*ntp+1], a[1], r2, r3);
            }
        }
        __syncthreads();
    }

    #pragma unroll
    for (int mt=0; mt<2; mt++) {
        int row = wm*32 + mt*16 + (lane>>2);
        #pragma unroll
        for (int nt=0; nt<8; nt++) {
            int col = nt0*128 + wn*64 + nt*8 + (lane&3)*2;
            size_t base = ((size_t)(ks*4 + b)*512 + col)*96;
            if (row < 96) {
                part[base + row]      = c[mt][nt][0];
                part[base + 96 + row] = c[mt][nt][1];
            }
            if (row + 8 < 96) {
                part[base + row + 8]      = c[mt][nt][2];
                part[base + 96 + row + 8] = c[mt][nt][3];
            }
        }
    }
}

// ---------------- u,v = F @ A, F @ B ; blockIdx.y==16 -> ws ----------------
__global__ void __launch_bounds__(256) uvws_k(const float* __restrict__ cpart,
                                              const float* __restrict__ e4b,
                                              const float* __restrict__ g1w,
                                              const float* __restrict__ g1b,
                                              const float* __restrict__ sen,
                                              float* __restrict__ u, float* __restrict__ v,
                                              float* __restrict__ ws)
{
    __shared__ float sF[128*96];
    const int b  = blockIdx.x;
    const int tid = threadIdx.x;
    const int PS = 4*512*96;

    if (blockIdx.y == 16) {
        float* ss = sF;
        const int n = tid;
        for (int k=n;k<384;k+=256) ss[k]=sen[b*384+k];
        __syncthreads();
        float acc = g1b[n];
        for (int k=0;k<384;k++) acc = fmaf(ss[k], g1w[(1028+k)*256+n], acc);
        ws[b*256+n]=acc;
        return;
    }

    const int n0 = blockIdx.y*16;
    const int n  = tid & 15;
    const int pg = tid >> 4;
    float au[6], av[6];
    #pragma unroll
    for (int i=0;i<6;i++){ au[i]=0.f; av[i]=0.f; }

    for (int k0=0; k0<512; k0+=128) {
        __syncthreads();
        for (int idx=tid; idx<128*96; idx+=256) {
            int kk = idx/96, p = idx - kk*96;
            int base = (b*512 + k0 + kk)*96 + p;
            float vv = cpart[base] + cpart[base+PS] + cpart[base+2*PS] + cpart[base+3*PS]
                     + e4b[k0+kk];
            sF[kk*96 + p] = fmaxf(vv, 0.f);
        }
        __syncthreads();
        for (int kk=0; kk<128; kk++) {
            float wu = g1w[(k0+kk)*256 + n0 + n];
            float wv = g1w[(514 + k0+kk)*256 + n0 + n];
            const float* fr = &sF[kk*96 + pg*6];
            #pragma unroll
            for (int i=0;i<6;i++){
                float f = fr[i];
                au[i] = fmaf(f, wu, au[i]);
                av[i] = fmaf(f, wv, av[i]);
            }
        }
    }
    {
        float wu0 = g1w[512*256 + n0 + n], wu1 = g1w[513*256 + n0 + n];
        float wv0 = g1w[(514+512)*256 + n0 + n], wv1 = g1w[(514+513)*256 + n0 + n];
        #pragma unroll
        for (int i=0;i<6;i++){
            int p = pg*6 + i;
            float fx = -1.f + (2.f*(float)(p/8))/11.f;
            float fy = -1.f + (2.f*(float)(p%8))/7.f;
            au[i] += fx*wu0 + fy*wu1;
            av[i] += fx*wv0 + fy*wv1;
        }
    }
    #pragma unroll
    for (int i=0;i<6;i++){
        int p = pg*6 + i;
        u[(b*96+p)*256 + n0 + n] = au[i];
        v[(b*96+p)*256 + n0 + n] = av[i];
    }
}

// ---------------- h2: M=64 N=256 per block, rows built once ----------------
static constexpr int H2_DYN = 5120 + 2*20480;   // A 64x40 + B 2 stages x 256x40
__global__ void __launch_bounds__(256,2) h2_mma_k(
    const float* __restrict__ u, const float* __restrict__ v,
    const float* __restrict__ ws,
    const __half* __restrict__ w2thi,
    const float* __restrict__ b2, __half* __restrict__ a16)
{
    extern __shared__ __align__(16) char dsm[];
    __half* sA = (__half*)dsm;                       // 64*40
    __shared__ float sws[256];
    __shared__ float sb2[256];

    const int tid = threadIdx.x;
    const int wid = tid >> 5, lane = tid & 31;
    const int wm = wid >> 2, wn = wid & 3;
    const int r0 = blockIdx.x*64;
    const int b  = r0/9216;

    sws[tid] = ws[b*256 + tid];
    sb2[tid] = b2[tid];

    const int arow = tid >> 2;            // 0..63
    const int kh   = (tid & 3)*8;
    const int rr   = (r0 + arow) - b*9216;
    const int ii   = rr/96, jj = rr - ii*96;
    const float* up = u + (b*96 + jj)*256 + kh;
    const float* vp = v + (b*96 + ii)*256 + kh;

    const uint32_t dsb = smem_u32(dsm);

    auto issueB = [&](int cn, int stage) {
        const int koff = cn*32;
        const uint32_t dH = dsb + 5120 + stage*20480;
        #pragma unroll
        for (int i2=0;i2<4;i2++){
            int cidx = tid + i2*256;
            int row = cidx >> 2, g = cidx & 3;
            cp16(dH + row*80 + g*16, w2thi + row*256 + koff + g*8);
        }
        CP_COMMIT();
    };

    float c[2][8][4];
    #pragma unroll
    for (int mt=0;mt<2;mt++)
        #pragma unroll
        for (int nt=0;nt<8;nt++)
            #pragma unroll
            for (int e=0;e<4;e++) c[mt][nt][e]=0.f;

    issueB(0, 0);

    for (int ch = 0; ch < 8; ch++) {
        CP_WAIT0();
        __syncthreads();
        {
            const int koff = ch*32;
            float uf[8], vf[8];
            *(float4*)&uf[0] = *(const float4*)(up + koff);
            *(float4*)&uf[4] = *(const float4*)(up + koff + 4);
            *(float4*)&vf[0] = *(const float4*)(vp + koff);
            *(float4*)&vf[4] = *(const float4*)(vp + koff + 4);
            __half hv[8];
            const float* wsp = &sws[koff + kh];
            #pragma unroll
            for (int e=0;e<8;e++) hv[e] = __float2half(fmaxf(uf[e]+vf[e]+wsp[e], 0.f));
            *(uint4*)&sA[arow*40 + kh] = *(const uint4*)hv;
        }
        if (ch < 7) issueB(ch+1, (ch+1)&1);
        __syncthreads();

        const uint32_t sAb = dsb;
        const uint32_t sH = dsb + 5120 + (ch&1)*20480;
        #pragma unroll
        for (int ks=0; ks<2; ks++) {
            uint32_t a[2][4];
            #pragma unroll
            for (int mt=0; mt<2; mt++) {
                int row = wm*32 + mt*16 + (lane&7) + ((lane>>3)&1)*8;
                int col = ((lane>>4)&1)*8 + ks*16;
                ldm_x4(a[mt][0],a[mt][1],a[mt][2],a[mt][3], sAb + (row*40 + col)*2);
            }
            #pragma unroll
            for (int ntp=0; ntp<4; ntp++) {
                int rn = wn*64 + ntp*16 + (lane&7) + ((lane>>4)&1)*8;
                int ck = ((lane>>3)&1)*8 + ks*16;
                uint32_t r0r,r1r,r2r,r3r;
                ldm_x4(r0r,r1r,r2r,r3r, sH + (rn*40 + ck)*2);
                mma_f16(c[0][2*ntp],   a[0], r0r, r1r);
                mma_f16(c[0][2*ntp+1], a[0], r2r, r3r);
                mma_f16(c[1][2*ntp],   a[1], r0r, r1r);
                mma_f16(c[1][2*ntp+1], a[1], r2r, r3r);
            }
        }
    }

    #pragma unroll
    for (int mt=0; mt<2; mt++) {
        int row_l = r0 + wm*32 + mt*16 + (lane>>2);
        #pragma unroll
        for (int nt=0; nt<8; nt++) {
            int col = wn*64 + nt*8 + (lane&3)*2;
            float b0 = sb2[col], b1 = sb2[col+1];
            __half2 lo2 = __floats2half2_rn(fmaxf(c[mt][nt][0]+b0,0.f), fmaxf(c[mt][nt][1]+b1,0.f));
            __half2 hi2 = __floats2half2_rn(fmaxf(c[mt][nt][2]+b0,0.f), fmaxf(c[mt][nt][3]+b1,0.f));
            *(__half2*)&a16[(size_t)row_l*256 + col]     = lo2;
            *(__half2*)&a16[(size_t)(row_l+8)*256 + col] = hi2;
        }
    }
}

// ---------------- g3: B resident (4 chunks), 2 mtiles per block, A 2-stage ------
static constexpr int G3_TILE  = 18432;
static constexpr int G3_AOFF  = 4*G3_TILE;       // 73728
static constexpr int G3_DYN   = G3_AOFF + 2*G3_TILE;  // 110592
__global__ void __launch_bounds__(256,2) g3_mma_k(
    const __half* __restrict__ a16,
    const __half* __restrict__ wthi,
    const float* __restrict__ b3, float* __restrict__ part)
{
    extern __shared__ __align__(16) char dsm[];
    __shared__ float sbias[128];
    __shared__ float spart[4][128];

    const int tid  = threadIdx.x;
    const int wid  = tid >> 5;
    const int lane = tid & 31;
    const int wm   = wid >> 1;
    const int wn   = wid & 1;
    const int ntile = blockIdx.y;

    if (tid < 128) sbias[tid] = b3[ntile*128 + tid];

    const __half* A0 = a16 + (size_t)blockIdx.x*128*256;
    const __half* A1 = a16 + (size_t)(blockIdx.x+144)*128*256;
    const __half* Wh = wthi + (size_t)ntile*128*256;
    const uint32_t dsb = smem_u32(dsm);

    float c[2][8][4];
    #pragma unroll
    for (int mt=0;mt<2;mt++)
        #pragma unroll
        for (int nt=0;nt<8;nt++)
            #pragma unroll
            for (int e=0;e<4;e++) c[mt][nt][e]=0.f;

    // load all 4 B chunks as one commit group
    {
        #pragma unroll
        for (int cn=0; cn<4; cn++) {
            const int koff = cn*64;
            const uint32_t dB = dsb + cn*G3_TILE;
            #pragma unroll
            for (int i2=0;i2<4;i2++){
                int cidx = tid + i2*256;
                int row = cidx >> 3, g = cidx & 7;
                cp16(dB + row*144 + g*16, Wh + row*256 + koff + g*8);
            }
        }
        CP_COMMIT();
    }

    auto issueA = [&](const __half* Am, int cn, int stage) {
        const int koff = cn*64;
        const uint32_t dA = dsb + G3_AOFF + stage*G3_TILE;
        #pragma unroll
        for (int i2=0;i2<4;i2++){
            int cidx = tid + i2*256;
            int row = cidx >> 3, g = cidx & 7;
            cp16(dA + row*144 + g*16, Am + row*256 + koff + g*8);
        }
        CP_COMMIT();
    };

    auto compute = [&](int cn, int stage) {
        const uint32_t sAb = dsb + G3_AOFF + stage*G3_TILE;
        const uint32_t sB  = dsb + cn*G3_TILE;
        #pragma unroll
        for (int ks=0; ks<4; ks++) {
            uint32_t a[2][4];
            #pragma unroll
            for (int mt=0; mt<2; mt++) {
                int row = wm*32 + mt*16 + (lane&7) + ((lane>>3)&1)*8;
                int col = ((lane>>4)&1)*8 + ks*16;
                ldm_x4(a[mt][0],a[mt][1],a[mt][2],a[mt][3], sAb + (row*72 + col)*2);
            }
            #pragma unroll
            for (int ntp=0; ntp<4; ntp++) {
                int rn = wn*64 + ntp*16 + (lane&7) + ((lane>>4)&1)*8;
                int ck = ((lane>>3)&1)*8 + ks*16;
                uint32_t r0,r1,r2,r3;
                ldm_x4(r0,r1,r2,r3, sB + (rn*72 + ck)*2);
                mma_f16(c[0][2*ntp],   a[0], r0, r1);
                mma_f16(c[0][2*ntp+1], a[0], r2, r3);
                mma_f16(c[1][2*ntp],   a[1], r0, r1);
                mma_f16(c[1][2*ntp+1], a[1], r2, r3);
            }
        }
    };

    auto epilogue = [&](int mtile) {
        #pragma unroll
        for (int nt=0; nt<8; nt++) {
            int ncol = wn*64 + nt*8 + (lane&3)*2;
            float bias0 = sbias[ncol];
            float bias1 = sbias[ncol+1];
            float t0 = 0.f, t1 = 0.f;
            #pragma unroll
            for (int mt=0; mt<2; mt++) {
                t0 += fmaxf(c[mt][nt][0] + bias0, 0.f) + fmaxf(c[mt][nt][2] + bias0, 0.f);
                t1 += fmaxf(c[mt][nt][1] + bias1, 0.f) + fmaxf(c[mt][nt][3] + bias1, 0.f);
            }
            t0 += __shfl_xor_sync(0xFFFFFFFFu, t0, 4);
            t0 += __shfl_xor_sync(0xFFFFFFFFu, t0, 8);
            t0 += __shfl_xor_sync(0xFFFFFFFFu, t0, 16);
            t1 += __shfl_xor_sync(0xFFFFFFFFu, t1, 4);
            t1 += __shfl_xor_sync(0xFFFFFFFFu, t1, 8);
            t1 += __shfl_xor_sync(0xFFFFFFFFu, t1, 16);
            if (lane < 4) {
                spart[wm][wn*64 + nt*8 + lane*2]     = t0;
                spart[wm][wn*64 + nt*8 + lane*2 + 1] = t1;
            }
        }
        __syncthreads();
        if (tid < 128) {
            float s = spart[0][tid] + spart[1][tid] + spart[2][tid] + spart[3][tid];
            part[(size_t)mtile*3072 + ntile*128 + tid] = s;
        }
        __syncthreads();
        #pragma unroll
        for (int mt=0;mt<2;mt++)
            #pragma unroll
            for (int nt=0;nt<8;nt++)
                #pragma unroll
                for (int e=0;e<4;e++) c[mt][nt][e]=0.f;
    };

    issueA(A0, 0, 0);
    issueA(A0, 1, 1);

    // m0: chunks 0..3 (stage = ch&1); prefetch A0 ch+2 then A1 chunks
    CP_WAIT1(); __syncthreads(); compute(0,0); __syncthreads(); issueA(A0,2,0);
    CP_WAIT1(); __syncthreads(); compute(1,1); __syncthreads(); issueA(A0,3,1);
    CP_WAIT1(); __syncthreads(); compute(2,0); __syncthreads(); issueA(A1,0,0);
    CP_WAIT1(); __syncthreads(); compute(3,1); __syncthreads(); issueA(A1,1,1);
    epilogue(blockIdx.x);
    // m1
    CP_WAIT1(); __syncthreads(); compute(0,0); __syncthreads(); issueA(A1,2,0);
    CP_WAIT1(); __syncthreads(); compute(1,1); __syncthreads(); issueA(A1,3,1);
    CP_WAIT1(); __syncthreads(); compute(2,0); __syncthreads();
    CP_WAIT0(); __syncthreads(); compute(3,1);
    epilogue(blockIdx.x + 144);
}

// ---------------- final reduce over 72 row-tiles per batch ----------------
__global__ void final_reduce_k(const float* __restrict__ part, float* __restrict__ outp)
{
    int idx = blockIdx.x*blockDim.x + threadIdx.x;
    if (idx >= 4*3072) return;
    int b = idx/3072, n = idx - b*3072;
    float s = 0.f;
    for (int t=0;t<72;t++) s += part[(b*72+t)*3072 + n];
    outp[idx] = s;
}

// ---------------- launch ----------------
extern "C" void kernel_launch(void* const* d_in, const int* in_sizes, int n_in,
                              void* d_out, int out_size)
{
    const float* x      = (const float*)d_in[0];
    const float* sen    = (const float*)d_in[1];
    const float* e1w    = (const float*)d_in[2];
    const float* e1b    = (const float*)d_in[3];
    const float* e2w    = (const float*)d_in[4];
    const float* e2b    = (const float*)d_in[5];
    const float* e3w    = (const float*)d_in[6];
    const float* e3b    = (const float*)d_in[7];
    const float* e4w    = (const float*)d_in[8];
    const float* e4b    = (const float*)d_in[9];
    const float* g1w    = (const float*)d_in[10];
    const float* g1b    = (const float*)d_in[11];
    const float* g2w    = (const float*)d_in[12];
    const float* g2b    = (const float*)d_in[13];
    const float* g3w    = (const float*)d_in[14];
    const float* g3b    = (const float*)d_in[15];
    float* outp = (float*)d_out;

    float *pp1,*pp2,*pc3,*pp3,*pcpart,*pu,*pv,*pws,*ppart;
    __half *pa4,*pw4hi,*pw4lo,*pa16,*pwthi,*pw2thi;
    cudaGetSymbolAddress((void**)&pp1,  g_p1);
    cudaGetSymbolAddress((void**)&pp2,  g_p2);
    cudaGetSymbolAddress((void**)&pc3,  g_c3part);
    cudaGetSymbolAddress((void**)&pp3,  g_p3);
    cudaGetSymbolAddress((void**)&pa4,  g_a4);
    cudaGetSymbolAddress((void**)&pw4hi,g_w4hi);
    cudaGetSymbolAddress((void**)&pw4lo,g_w4lo);
    cudaGetSymbolAddress((void**)&pcpart,g_cpart);
    cudaGetSymbolAddress((void**)&pu,   g_u);
    cudaGetSymbolAddress((void**)&pv,   g_v);
    cudaGetSymbolAddress((void**)&pws,  g_ws);
    cudaGetSymbolAddress((void**)&pa16, g_a16);
    cudaGetSymbolAddress((void**)&pwthi,g_wthi);
    cudaGetSymbolAddress((void**)&pw2thi,g_w2thi);
    cudaGetSymbolAddress((void**)&ppart,g_part);

    cudaFuncSetAttribute(h2_mma_k, cudaFuncAttributeMaxDynamicSharedMemorySize, H2_DYN);
    cudaFuncSetAttribute(g3_mma_k, cudaFuncAttributeMaxDynamicSharedMemorySize, G3_DYN);
    cudaFuncSetAttribute(conv4_mma_k, cudaFuncAttributeMaxDynamicSharedMemorySize, C4_DYN);

    // encoder
    conv3x3_pool<3,3,64,32,8,64,96,4><<<dim3(4,2,16), dim3(96,4)>>>(x, e1w, e1b, pp1);
    conv3x3_pool<64,16,128,16,4,32,48,4><<<dim3(4,8,8), dim3(48,4)>>>(pp1, e2w, e2b, pp2);
    conv3_split_k<<<dim3(4,16,4), dim3(48,4)>>>(pp2, e3w, pc3);
    combine3_k<<<(4*256*96+255)/256,256>>>(pc3, e3b, pp3);
    prep_all_k<<<(256*3072+256*256+512*2304+4*128*2304+255)/256,256>>>(
        g3w, g2w, e4w, pp3, pwthi, pw2thi, pw4hi, pw4lo, pa4);
    conv4_mma_k<<<dim3(4,4,4),256,C4_DYN>>>(pa4, pw4hi, pw4lo, pcpart);

    // relation net
    uvws_k<<<dim3(4,17),256>>>(pcpart, e4b, g1w, g1b, sen, pu, pv, pws);
    h2_mma_k<<<dim3(576,1),256,H2_DYN>>>(pu, pv, pws, pw2thi, g2b, pa16);
    g3_mma_k<<<dim3(144,24),256,G3_DYN>>>(pa16, pwthi, g3b, ppart);
    final_reduce_k<<<48,256>>>(ppart, outp);
}